// round 10
// baseline (speedup 1.0000x reference)
#include <cuda_runtime.h>
#include <cstdint>

// Problem constants (shapes fixed by the dataset problem)
#define ROWS 64            // B*N
#define PP   147456        // H*W
#define KCLS 3
#define NBIN 4096
#define THREADS 256

// k1 chunking
#define CHUNKS1 16
#define CHUNK1  (PP / CHUNKS1)           // 9216
#define ITERS1  (CHUNK1 / (THREADS*4))   // 9

// k3 chunking (fine: low regs, high occupancy)
#define CHUNKS3 48
#define CHUNK3  (PP / CHUNKS3)           // 3072
#define ITERS3  (CHUNK3 / (THREADS*4))   // 3

#define CNT_SHIFT 46
#define FX_MASK   ((1ull << CNT_SHIFT) - 1ull)
#define FX_SCALE  4194304.0f             // 2^22 per-element fixed point
#define TOT_MUL   256ull                 // 2^22 -> 2^30 for g_total
#define FXD       1073741824.0           // 2^30

// -------- scratch (no allocations allowed; device globals; self-cleaning) ----
__device__ float g_nll [(size_t)ROWS * PP];
__device__ unsigned int g_hist[ROWS * NBIN];          // zeroed by k2 after use
__device__ unsigned long long g_fine[ROWS * NBIN];    // zeroed by k4 after use
__device__ int g_bstar[ROWS];                         // overwritten by k2
__device__ int g_needed[ROWS];                        // overwritten by k2
__device__ unsigned long long g_total;                // zeroed by k5 after use

__device__ __forceinline__ unsigned int nbits(float v) {
    return (v > 0.0f) ? __float_as_uint(v) : 0u;      // nll >= 0
}

__device__ __forceinline__ unsigned long long fx_of(float v) {
    float c = fminf(v, 64.0f);                        // 46-bit safety cap
    return (unsigned long long)(c * FX_SCALE + 0.5f);
}

__device__ __forceinline__ float nllsel(int t, float a, float b, float c) {
    if (t == 255) return 0.0f;                        // ignore_index
    float v = (t == 0) ? a : (t == 1) ? b : c;
    return -v;
}

__device__ __forceinline__ int decode_m(const void* sp_ptr, int has_sp) {
    double sp = 1.0;
    if (has_sp) {
        unsigned int bits = *(const unsigned int*)sp_ptr;
        if (bits < 1024u) sp = (double)(int)bits;             // int32 scalar
        else              sp = (double)__uint_as_float(bits); // float32 scalar
    }
    if (sp > 1.0) sp = 1.0;
    if (sp < 0.0) sp = 0.0;
    double md = sp * 0.15 * (double)PP + (1.0 - sp) * (double)PP;
    int m = (int)md;
    if (m < 1) m = 1;
    if (m > PP) m = PP;
    return m;
}

// -------- K1: nll compute + buffer + per-row u32 histogram --------
__global__ void __launch_bounds__(THREADS) k1_nll(const float* __restrict__ inp,
                                                  const int*   __restrict__ tgt) {
    __shared__ unsigned int sh[NBIN];                 // 16 KB
    for (int i = threadIdx.x; i < NBIN; i += THREADS) sh[i] = 0u;
    __syncthreads();

    int row = blockIdx.x / CHUNKS1;
    int seg = blockIdx.x % CHUNKS1;
    size_t tbase = (size_t)row * PP + (size_t)seg * CHUNK1;
    const float* p0 = inp + (size_t)row * KCLS * PP + (size_t)seg * CHUNK1;
    const float* p1 = p0 + PP;
    const float* p2 = p0 + 2 * PP;
    const int*   tg = tgt + tbase;
    float*       ob = g_nll + tbase;

    int off0 = threadIdx.x * 4;
    int4   t4 = *(const int4*)(tg + off0);
    float4 a  = *(const float4*)(p0 + off0);
    float4 b  = *(const float4*)(p1 + off0);
    float4 c  = *(const float4*)(p2 + off0);

#pragma unroll
    for (int it = 0; it < ITERS1; ++it) {
        int4 t4n; float4 an, bn, cn;
        if (it + 1 < ITERS1) {
            int offn = (it + 1) * (THREADS * 4) + threadIdx.x * 4;
            t4n = *(const int4*)(tg + offn);
            an  = *(const float4*)(p0 + offn);
            bn  = *(const float4*)(p1 + offn);
            cn  = *(const float4*)(p2 + offn);
        }
        int off = it * (THREADS * 4) + threadIdx.x * 4;
        float4 o;
        o.x = nllsel(t4.x, a.x, b.x, c.x);
        o.y = nllsel(t4.y, a.y, b.y, c.y);
        o.z = nllsel(t4.z, a.z, b.z, c.z);
        o.w = nllsel(t4.w, a.w, b.w, c.w);
        atomicAdd(&sh[nbits(o.x) >> 19], 1u);
        atomicAdd(&sh[nbits(o.y) >> 19], 1u);
        atomicAdd(&sh[nbits(o.z) >> 19], 1u);
        atomicAdd(&sh[nbits(o.w) >> 19], 1u);
        *(float4*)(ob + off) = o;
        t4 = t4n; a = an; b = bn; c = cn;
    }
    __syncthreads();
    for (int i = threadIdx.x; i < NBIN; i += THREADS) {
        unsigned int v = sh[i];
        if (v) atomicAdd(&g_hist[row * NBIN + i], v);
    }
}

// -------- K2: threshold bin via suffix scan; zeroes g_hist after use --------
__global__ void __launch_bounds__(THREADS) k2_thresh(const void* sp_ptr, int has_sp) {
    int row = blockIdx.x;
    __shared__ unsigned int sh[NBIN];
    __shared__ unsigned int cs[THREADS];
    for (int i = threadIdx.x; i < NBIN; i += THREADS) {
        sh[i] = g_hist[row * NBIN + i];
        g_hist[row * NBIN + i] = 0u;                  // self-clean for next replay
    }
    __syncthreads();
    unsigned s = 0;
    int base = threadIdx.x * (NBIN / THREADS);        // 16 bins each
    for (int j = 0; j < NBIN / THREADS; ++j) s += sh[base + j];
    cs[threadIdx.x] = s;
    __syncthreads();
    if (threadIdx.x == 0) {
        unsigned m = (unsigned)decode_m(sp_ptr, has_sp);
        unsigned acc = 0, above = 0;
        int bstar = 0;
        for (int j = THREADS - 1; j >= 0; --j) {
            if (acc + cs[j] >= m) {
                for (int b = j * 16 + 15; b >= j * 16; --b) {
                    acc += sh[b];
                    if (acc >= m) { bstar = b; above = acc - sh[b]; break; }
                }
                break;
            }
            acc += cs[j];
        }
        g_bstar[row]  = bstar;
        g_needed[row] = (int)m - (int)above;
    }
}

// -------- K3: fx-sum above bstar; fine count+sum histogram of bstar bin ------
__global__ void __launch_bounds__(THREADS) k3_sum() {
    int row = blockIdx.x / CHUNKS3;
    unsigned bstar = (unsigned)g_bstar[row];
    size_t tbase = (size_t)row * PP + (size_t)(blockIdx.x % CHUNKS3) * CHUNK3;
    const float4* ib = (const float4*)(g_nll + tbase);
    unsigned long long* fine = g_fine + (size_t)row * NBIN;

    // Front-batch loads: 3 independent LDG.128 per thread.
    float4 r[ITERS3];
#pragma unroll
    for (int it = 0; it < ITERS3; ++it)
        r[it] = ib[it * THREADS + threadIdx.x];

    unsigned long long fx = 0ull;
#pragma unroll
    for (int it = 0; it < ITERS3; ++it) {
        float vv[4] = {r[it].x, r[it].y, r[it].z, r[it].w};
#pragma unroll
        for (int e = 0; e < 4; ++e) {
            float v = vv[e];
            unsigned bits = nbits(v);
            unsigned bin = bits >> 19;
            if (bin > bstar) {
                fx += fx_of(v);
            } else if (bin == bstar) {                // rare; fire-and-forget RED
                unsigned fb = (bits >> 7) & 0xFFFu;
                atomicAdd(&fine[fb], (1ull << CNT_SHIFT) | fx_of(v));
            }
        }
    }

    // warp shuffle reduction, then one cross-warp step
    __shared__ unsigned long long wred[THREADS / 32];
#pragma unroll
    for (int o = 16; o > 0; o >>= 1)
        fx += __shfl_xor_sync(0xffffffffu, fx, o);
    int wid = threadIdx.x >> 5;
    if ((threadIdx.x & 31) == 0) wred[wid] = fx;
    __syncthreads();
    if (threadIdx.x == 0) {
        unsigned long long t = 0ull;
#pragma unroll
        for (int w = 0; w < THREADS / 32; ++w) t += wred[w];
        if (t) atomicAdd(&g_total, t * TOT_MUL);
    }
}

// -------- K4: single scan of fine histogram; bin-mean boundary estimate ------
__global__ void __launch_bounds__(THREADS) k4_fine() {
    int row = blockIdx.x;
    int tid = threadIdx.x;
    int needed = g_needed[row];
    unsigned long long* fine = g_fine + (size_t)row * NBIN;

    __shared__ unsigned long long sh[NBIN];           // 32 KB
    __shared__ unsigned int cs[THREADS];
    for (int i = tid; i < NBIN; i += THREADS) {
        sh[i] = fine[i];
        fine[i] = 0ull;                               // self-clean for next replay
    }
    __syncthreads();
    if (needed <= 0) return;

    unsigned c = 0;
    int base = tid * (NBIN / THREADS);                // 16 bins each
    for (int j = 0; j < NBIN / THREADS; ++j)
        c += (unsigned)(sh[base + j] >> CNT_SHIFT);
    cs[tid] = c;
    __syncthreads();
    if (tid == 0) {
        unsigned acc = 0, above = 0;
        unsigned long long sum_above = 0ull;
        int b2 = 0;
        for (int j = THREADS - 1; j >= 0; --j) {
            unsigned cj = cs[j];
            // compute partial sums lazily only inside the terminal group
            if (acc + cj >= (unsigned)needed) {
                for (int b = j * 16 + 15; b >= j * 16; --b) {
                    unsigned long long v = sh[b];
                    unsigned bc = (unsigned)(v >> CNT_SHIFT);
                    acc += bc;
                    if (acc >= (unsigned)needed) { b2 = b; above = acc - bc; break; }
                    sum_above += (v & FX_MASK);
                }
                break;
            }
            acc += cj;
            // accumulate group sum
            unsigned long long gs = 0ull;
            for (int b = j * 16; b < j * 16 + 16; ++b) gs += (sh[b] & FX_MASK);
            sum_above += gs;
        }
        unsigned need2 = (unsigned)needed - above;
        unsigned long long v2 = sh[b2];
        unsigned cnt2 = (unsigned)(v2 >> CNT_SHIFT);  // >= need2 >= 1
        unsigned long long fx2 = v2 & FX_MASK;
        unsigned long long avg = cnt2 ? (fx2 / cnt2) : 0ull;
        unsigned long long contrib = sum_above + (unsigned long long)need2 * avg;
        if (contrib) atomicAdd(&g_total, contrib * TOT_MUL);
    }
}

// -------- K5: finalize mean; zeroes g_total for next replay --------
__global__ void k5_final(float* out, const void* sp_ptr, int has_sp) {
    if (threadIdx.x == 0 && blockIdx.x == 0) {
        int m = decode_m(sp_ptr, has_sp);
        double tot = (double)g_total / FXD;
        out[0] = (float)(tot / ((double)ROWS * (double)m));
        g_total = 0ull;                               // self-clean for next replay
    }
}

extern "C" void kernel_launch(void* const* d_in, const int* in_sizes, int n_in,
                              void* d_out, int out_size) {
    const float* inp = (const float*)d_in[0];
    const int*   tgt = (const int*)d_in[1];
    const void*  sp  = (n_in > 2) ? d_in[2] : nullptr;
    int has_sp = (n_in > 2) ? 1 : 0;
    (void)in_sizes; (void)out_size;

    k1_nll<<<ROWS * CHUNKS1, THREADS>>>(inp, tgt);
    k2_thresh<<<ROWS, THREADS>>>(sp, has_sp);
    k3_sum<<<ROWS * CHUNKS3, THREADS>>>();
    k4_fine<<<ROWS, THREADS>>>();
    k5_final<<<1, 32>>>((float*)d_out, sp, has_sp);
}

// round 11
// speedup vs baseline: 1.2863x; 1.2863x over previous
#include <cuda_runtime.h>
#include <cstdint>

// Problem constants (shapes fixed by the dataset problem)
#define ROWS 64            // B*N
#define PP   147456        // H*W
#define KCLS 3
#define NBIN 4096
#define NFINE 1024
#define THREADS 256

// k1 chunking
#define CHUNKS1 16
#define CHUNK1  (PP / CHUNKS1)           // 9216
#define ITERS1  (CHUNK1 / (THREADS*4))   // 9

// k3 chunking (fine: low regs, high occupancy)
#define CHUNKS3 48
#define CHUNK3  (PP / CHUNKS3)           // 3072
#define ITERS3  (CHUNK3 / (THREADS*4))   // 3

#define CNT_SHIFT 46
#define FX_MASK   ((1ull << CNT_SHIFT) - 1ull)
#define FX_SCALE  4194304.0f             // 2^22 per-element fixed point
#define TOT_MUL   256ull                 // 2^22 -> 2^30 for g_total
#define FXD       1073741824.0           // 2^30

// -------- scratch (no allocations allowed; device globals; self-cleaning) ----
__device__ float g_nll [(size_t)ROWS * PP];
__device__ unsigned int g_hist[ROWS * NBIN];          // zeroed by k2 after use
__device__ unsigned long long g_fine[ROWS * NFINE];   // zeroed by k4 after use
__device__ int g_bstar[ROWS];                         // overwritten by k2
__device__ int g_needed[ROWS];                        // overwritten by k2
__device__ unsigned long long g_total;                // zeroed by k5 after use

__device__ __forceinline__ unsigned int nbits(float v) {
    return (v > 0.0f) ? __float_as_uint(v) : 0u;      // nll >= 0
}

__device__ __forceinline__ unsigned long long fx_of(float v) {
    float c = fminf(v, 64.0f);                        // 46-bit safety cap
    return (unsigned long long)(c * FX_SCALE + 0.5f);
}

__device__ __forceinline__ float nllsel(int t, float a, float b, float c) {
    if (t == 255) return 0.0f;                        // ignore_index
    float v = (t == 0) ? a : (t == 1) ? b : c;
    return -v;
}

__device__ __forceinline__ int decode_m(const void* sp_ptr, int has_sp) {
    double sp = 1.0;
    if (has_sp) {
        unsigned int bits = *(const unsigned int*)sp_ptr;
        if (bits < 1024u) sp = (double)(int)bits;             // int32 scalar
        else              sp = (double)__uint_as_float(bits); // float32 scalar
    }
    if (sp > 1.0) sp = 1.0;
    if (sp < 0.0) sp = 0.0;
    double md = sp * 0.15 * (double)PP + (1.0 - sp) * (double)PP;
    int m = (int)md;
    if (m < 1) m = 1;
    if (m > PP) m = PP;
    return m;
}

// -------- K1: nll compute + buffer + per-row u32 histogram --------
__global__ void __launch_bounds__(THREADS) k1_nll(const float* __restrict__ inp,
                                                  const int*   __restrict__ tgt) {
    __shared__ unsigned int sh[NBIN];                 // 16 KB
    for (int i = threadIdx.x; i < NBIN; i += THREADS) sh[i] = 0u;
    __syncthreads();

    int row = blockIdx.x / CHUNKS1;
    int seg = blockIdx.x % CHUNKS1;
    size_t tbase = (size_t)row * PP + (size_t)seg * CHUNK1;
    const float* p0 = inp + (size_t)row * KCLS * PP + (size_t)seg * CHUNK1;
    const float* p1 = p0 + PP;
    const float* p2 = p0 + 2 * PP;
    const int*   tg = tgt + tbase;
    float*       ob = g_nll + tbase;

    int off0 = threadIdx.x * 4;
    int4   t4 = *(const int4*)(tg + off0);
    float4 a  = *(const float4*)(p0 + off0);
    float4 b  = *(const float4*)(p1 + off0);
    float4 c  = *(const float4*)(p2 + off0);

#pragma unroll
    for (int it = 0; it < ITERS1; ++it) {
        int4 t4n; float4 an, bn, cn;
        if (it + 1 < ITERS1) {
            int offn = (it + 1) * (THREADS * 4) + threadIdx.x * 4;
            t4n = *(const int4*)(tg + offn);
            an  = *(const float4*)(p0 + offn);
            bn  = *(const float4*)(p1 + offn);
            cn  = *(const float4*)(p2 + offn);
        }
        int off = it * (THREADS * 4) + threadIdx.x * 4;
        float4 o;
        o.x = nllsel(t4.x, a.x, b.x, c.x);
        o.y = nllsel(t4.y, a.y, b.y, c.y);
        o.z = nllsel(t4.z, a.z, b.z, c.z);
        o.w = nllsel(t4.w, a.w, b.w, c.w);
        atomicAdd(&sh[nbits(o.x) >> 19], 1u);
        atomicAdd(&sh[nbits(o.y) >> 19], 1u);
        atomicAdd(&sh[nbits(o.z) >> 19], 1u);
        atomicAdd(&sh[nbits(o.w) >> 19], 1u);
        *(float4*)(ob + off) = o;
        t4 = t4n; a = an; b = bn; c = cn;
    }
    __syncthreads();
    for (int i = threadIdx.x; i < NBIN; i += THREADS) {
        unsigned int v = sh[i];
        if (v) atomicAdd(&g_hist[row * NBIN + i], v);
    }
}

// -------- K2: threshold bin via suffix scan; zeroes g_hist after use --------
__global__ void __launch_bounds__(THREADS) k2_thresh(const void* sp_ptr, int has_sp) {
    int row = blockIdx.x;
    __shared__ unsigned int sh[NBIN];
    __shared__ unsigned int cs[THREADS];
    for (int i = threadIdx.x; i < NBIN; i += THREADS) {
        sh[i] = g_hist[row * NBIN + i];
        g_hist[row * NBIN + i] = 0u;                  // self-clean for next replay
    }
    __syncthreads();
    unsigned s = 0;
    int base = threadIdx.x * (NBIN / THREADS);        // 16 bins each
    for (int j = 0; j < NBIN / THREADS; ++j) s += sh[base + j];
    cs[threadIdx.x] = s;
    __syncthreads();
    if (threadIdx.x == 0) {
        unsigned m = (unsigned)decode_m(sp_ptr, has_sp);
        unsigned acc = 0, above = 0;
        int bstar = 0;
        for (int j = THREADS - 1; j >= 0; --j) {
            if (acc + cs[j] >= m) {
                for (int b = j * 16 + 15; b >= j * 16; --b) {
                    acc += sh[b];
                    if (acc >= m) { bstar = b; above = acc - sh[b]; break; }
                }
                break;
            }
            acc += cs[j];
        }
        g_bstar[row]  = bstar;
        g_needed[row] = (int)m - (int)above;
    }
}

// -------- K3: fx-sum above bstar; 1024-bin fine count+sum of bstar bin -------
__global__ void __launch_bounds__(THREADS) k3_sum() {
    int row = blockIdx.x / CHUNKS3;
    unsigned bstar = (unsigned)g_bstar[row];
    size_t tbase = (size_t)row * PP + (size_t)(blockIdx.x % CHUNKS3) * CHUNK3;
    const float4* ib = (const float4*)(g_nll + tbase);
    unsigned long long* fine = g_fine + (size_t)row * NFINE;

    // Front-batch loads: 3 independent LDG.128 per thread.
    float4 r[ITERS3];
#pragma unroll
    for (int it = 0; it < ITERS3; ++it)
        r[it] = ib[it * THREADS + threadIdx.x];

    unsigned long long fx = 0ull;
#pragma unroll
    for (int it = 0; it < ITERS3; ++it) {
        float vv[4] = {r[it].x, r[it].y, r[it].z, r[it].w};
#pragma unroll
        for (int e = 0; e < 4; ++e) {
            float v = vv[e];
            unsigned bits = nbits(v);
            unsigned bin = bits >> 19;
            if (bin > bstar) {
                fx += fx_of(v);
            } else if (bin == bstar) {                // rare; fire-and-forget RED
                unsigned fb = (bits >> 9) & (NFINE - 1u);
                atomicAdd(&fine[fb], (1ull << CNT_SHIFT) | fx_of(v));
            }
        }
    }

    // warp shuffle reduction, then one cross-warp step
    __shared__ unsigned long long wred[THREADS / 32];
#pragma unroll
    for (int o = 16; o > 0; o >>= 1)
        fx += __shfl_xor_sync(0xffffffffu, fx, o);
    int wid = threadIdx.x >> 5;
    if ((threadIdx.x & 31) == 0) wred[wid] = fx;
    __syncthreads();
    if (threadIdx.x == 0) {
        unsigned long long t = 0ull;
#pragma unroll
        for (int w = 0; w < THREADS / 32; ++w) t += wred[w];
        if (t) atomicAdd(&g_total, t * TOT_MUL);
    }
}

// -------- K4: scan of 1024-bin fine histogram; bin-mean boundary estimate ----
__global__ void __launch_bounds__(THREADS) k4_fine() {
    int row = blockIdx.x;
    int tid = threadIdx.x;
    int needed = g_needed[row];
    unsigned long long* fine = g_fine + (size_t)row * NFINE;

    __shared__ unsigned long long sh[NFINE];          // 8 KB
    __shared__ unsigned int cs[THREADS];

    // front-batched load + zero (4 independent u64 per thread)
    unsigned long long v0 = fine[tid];
    unsigned long long v1 = fine[tid + 256];
    unsigned long long v2 = fine[tid + 512];
    unsigned long long v3 = fine[tid + 768];
    fine[tid]       = 0ull;                           // self-clean
    fine[tid + 256] = 0ull;
    fine[tid + 512] = 0ull;
    fine[tid + 768] = 0ull;
    sh[tid]       = v0;
    sh[tid + 256] = v1;
    sh[tid + 512] = v2;
    sh[tid + 768] = v3;
    __syncthreads();
    if (needed <= 0) return;

    // each thread owns 4 consecutive bins
    unsigned c = 0;
    int base = tid * (NFINE / THREADS);               // 4 bins each
#pragma unroll
    for (int j = 0; j < NFINE / THREADS; ++j)
        c += (unsigned)(sh[base + j] >> CNT_SHIFT);
    cs[tid] = c;
    __syncthreads();
    if (tid == 0) {
        unsigned acc = 0, above = 0;
        unsigned long long sum_above = 0ull;
        int b2 = 0;
        for (int j = THREADS - 1; j >= 0; --j) {
            unsigned cj = cs[j];
            if (acc + cj >= (unsigned)needed) {
                for (int b = j * 4 + 3; b >= j * 4; --b) {
                    unsigned long long v = sh[b];
                    unsigned bc = (unsigned)(v >> CNT_SHIFT);
                    acc += bc;
                    if (acc >= (unsigned)needed) { b2 = b; above = acc - bc; break; }
                    sum_above += (v & FX_MASK);
                }
                break;
            }
            acc += cj;
            unsigned long long gs = 0ull;
            for (int b = j * 4; b < j * 4 + 4; ++b) gs += (sh[b] & FX_MASK);
            sum_above += gs;
        }
        unsigned need2 = (unsigned)needed - above;
        unsigned long long vb = sh[b2];
        unsigned cnt2 = (unsigned)(vb >> CNT_SHIFT);  // >= need2 >= 1
        unsigned long long fx2 = vb & FX_MASK;
        unsigned long long avg = cnt2 ? (fx2 / cnt2) : 0ull;
        unsigned long long contrib = sum_above + (unsigned long long)need2 * avg;
        if (contrib) atomicAdd(&g_total, contrib * TOT_MUL);
    }
}

// -------- K5: finalize mean; zeroes g_total for next replay --------
__global__ void k5_final(float* out, const void* sp_ptr, int has_sp) {
    if (threadIdx.x == 0 && blockIdx.x == 0) {
        int m = decode_m(sp_ptr, has_sp);
        double tot = (double)g_total / FXD;
        out[0] = (float)(tot / ((double)ROWS * (double)m));
        g_total = 0ull;                               // self-clean for next replay
    }
}

extern "C" void kernel_launch(void* const* d_in, const int* in_sizes, int n_in,
                              void* d_out, int out_size) {
    const float* inp = (const float*)d_in[0];
    const int*   tgt = (const int*)d_in[1];
    const void*  sp  = (n_in > 2) ? d_in[2] : nullptr;
    int has_sp = (n_in > 2) ? 1 : 0;
    (void)in_sizes; (void)out_size;

    k1_nll<<<ROWS * CHUNKS1, THREADS>>>(inp, tgt);
    k2_thresh<<<ROWS, THREADS>>>(sp, has_sp);
    k3_sum<<<ROWS * CHUNKS3, THREADS>>>();
    k4_fine<<<ROWS, THREADS>>>();
    k5_final<<<1, 32>>>((float*)d_out, sp, has_sp);
}